// round 3
// baseline (speedup 1.0000x reference)
#include <cuda_runtime.h>
#include <math.h>

#define BATCH 4
#define NN 4096
#define HID 128
#define G4 512
#define CAP 640

// ---------------- device scratch ----------------
__device__ float g_dinv[BATCH * NN];
__device__ int   g_cnt[BATCH * NN];
__device__ unsigned short g_idx[(size_t)BATCH * NN * CAP];   // ~21 MB
__device__ float g_dyn[BATCH * HID * HID];                   // conv out [b][time=o][f=t]
__device__ float g_zx[BATCH * HID * G4];                     // x-part of gates + biases
__device__ float g_lwm[BATCH * HID * HID];                   // lstm hidden [b][t][h]
__device__ float g_xws[(size_t)BATCH * NN * HID];            // d_inv[j] * (x @ lw)[j,:]

__device__ __forceinline__ float sigf(float x) { return 1.f / (1.f + __expf(-x)); }

// ---------------- pass 1: degree + sparse index build (one warp per row) ----------------
__global__ void k_rowsum(const float* __restrict__ A) {
    int warp = (blockIdx.x * blockDim.x + threadIdx.x) >> 5;
    int lane = threadIdx.x & 31;
    const float4* Ar = (const float4*)(A + (size_t)warp * NN);
    unsigned short* idx = g_idx + (size_t)warp * CAP;
    unsigned lt = (1u << lane) - 1u;
    float s = 0.f;
    int base = 0;
    for (int k = 0; k < NN / 128; k++) {
        float4 a = Ar[k * 32 + lane];
        s += (a.x + a.y) + (a.z + a.w);
        int col = (k * 32 + lane) * 4;
        unsigned m;
        m = __ballot_sync(0xffffffffu, a.x != 0.f);
        if (a.x != 0.f) { int p = base + __popc(m & lt); if (p < CAP) idx[p] = (unsigned short)col; }
        base += __popc(m);
        m = __ballot_sync(0xffffffffu, a.y != 0.f);
        if (a.y != 0.f) { int p = base + __popc(m & lt); if (p < CAP) idx[p] = (unsigned short)(col + 1); }
        base += __popc(m);
        m = __ballot_sync(0xffffffffu, a.z != 0.f);
        if (a.z != 0.f) { int p = base + __popc(m & lt); if (p < CAP) idx[p] = (unsigned short)(col + 2); }
        base += __popc(m);
        m = __ballot_sync(0xffffffffu, a.w != 0.f);
        if (a.w != 0.f) { int p = base + __popc(m & lt); if (p < CAP) idx[p] = (unsigned short)(col + 3); }
        base += __popc(m);
    }
    #pragma unroll
    for (int o = 16; o; o >>= 1) s += __shfl_xor_sync(0xffffffffu, s, o);
    if (lane == 0) { g_cnt[warp] = base; g_dinv[warp] = rsqrtf(s + 1.f); }
}

// ---------------- conv1d (NCH, pad 1): dyn[b][o][t] ----------------
__global__ void k_conv(const float* __restrict__ x, const float* __restrict__ cw,
                       const float* __restrict__ cb) {
    int b = blockIdx.x >> 7, o = blockIdx.x & 127, t = threadIdx.x;
    __shared__ float w[HID * 3];
    for (int i = threadIdx.x; i < HID * 3; i += blockDim.x) w[i] = cw[o * HID * 3 + i];
    __syncthreads();
    float acc = cb[o];
    const float* xb = x + ((size_t)b * NN + (NN - HID)) * HID;
    for (int i = 0; i < HID; i++) {
        const float* xr = xb + i * HID;
        float xm = (t > 0) ? xr[t - 1] : 0.f;
        float x0 = xr[t];
        float xp = (t < HID - 1) ? xr[t + 1] : 0.f;
        acc += xm * w[i * 3] + x0 * w[i * 3 + 1] + xp * w[i * 3 + 2];
    }
    g_dyn[(b * HID + o) * HID + t] = acc;
}

// ---------------- zx[b][t][g] = dyn[b][t] @ w_ih^T + b_ih + b_hh ----------------
__global__ void k_zx(const float* __restrict__ wih, const float* __restrict__ bih,
                     const float* __restrict__ bhh) {
    int b = blockIdx.x >> 2;
    int t0 = (blockIdx.x & 3) * 32;
    int g = threadIdx.x;
    __shared__ float4 dsh[32 * 32];   // [tt][f4]
    for (int i = threadIdx.x; i < 32 * 32; i += blockDim.x)
        dsh[i] = ((const float4*)g_dyn)[(b * HID + t0 + (i >> 5)) * 32 + (i & 31)];
    __syncthreads();
    float acc[32];
    #pragma unroll
    for (int tt = 0; tt < 32; tt++) acc[tt] = 0.f;
    const float4* w4 = (const float4*)wih + g * 32;
    for (int c = 0; c < 4; c++) {
        float4 wv[8];
        #pragma unroll
        for (int j = 0; j < 8; j++) wv[j] = w4[c * 8 + j];
        #pragma unroll
        for (int tt = 0; tt < 32; tt++) {
            float s = 0.f;
            #pragma unroll
            for (int j = 0; j < 8; j++) {
                float4 dv = dsh[tt * 32 + c * 8 + j];
                s += wv[j].x * dv.x + wv[j].y * dv.y + wv[j].z * dv.z + wv[j].w * dv.w;
            }
            acc[tt] += s;
        }
    }
    float bias = bih[g] + bhh[g];
    for (int tt = 0; tt < 32; tt++) g_zx[(b * HID + t0 + tt) * G4 + g] = acc[tt] + bias;
}

// ---------------- LSTM recurrence: one CTA per batch ----------------
__global__ void __launch_bounds__(512, 1) k_lstm(const float* __restrict__ whh) {
    int b = blockIdx.x, g = threadIdx.x;
    extern __shared__ float4 wsv[];     // [16][512] : w_hh[g][64+4k .. 64+4k+3]
    __shared__ float hsh[HID];
    __shared__ float zsh[G4];
    const float4* w4 = (const float4*)whh;
    float4 wr[16];                       // w_hh[g][0:64]
    #pragma unroll
    for (int j = 0; j < 16; j++) wr[j] = w4[g * 32 + j];
    for (int i = threadIdx.x; i < 16 * 512; i += 512) {
        int k4 = i >> 9, gg = i & 511;
        wsv[i] = w4[gg * 32 + 16 + k4];
    }
    if (g < HID) hsh[g] = 0.f;
    float c = 0.f;
    for (int t = 0; t < HID; t++) {
        __syncthreads();
        float z = g_zx[(b * HID + t) * G4 + g];
        const float4* h4 = (const float4*)hsh;
        #pragma unroll
        for (int j = 0; j < 16; j++) {
            float4 hv = h4[j]; float4 wv = wr[j];
            z += wv.x * hv.x + wv.y * hv.y + wv.z * hv.z + wv.w * hv.w;
        }
        #pragma unroll
        for (int k = 0; k < 16; k++) {
            float4 hv = h4[16 + k]; float4 wv = wsv[k * 512 + g];
            z += wv.x * hv.x + wv.y * hv.y + wv.z * hv.z + wv.w * hv.w;
        }
        zsh[g] = z;
        __syncthreads();
        if (g < HID) {
            float iv = sigf(zsh[g]);
            float fv = sigf(zsh[HID + g]);
            float gv = tanhf(zsh[2 * HID + g]);
            float ov = sigf(zsh[3 * HID + g]);
            c = fv * c + iv * gv;
            float h = ov * tanhf(c);
            hsh[g] = h;
            g_lwm[(b * HID + t) * HID + g] = h;
        }
    }
}

// ---------------- xw_s[b][j][h] = d_inv[j] * (x[b][j] @ lw[b]) ----------------
__global__ void k_xw(const float* __restrict__ x) {
    int b = blockIdx.x >> 7;
    int r0 = (blockIdx.x & 127) * 32;
    int h = threadIdx.x;
    __shared__ float4 xs4[32 * 32];     // [r][f4]
    for (int i = threadIdx.x; i < 32 * 32; i += blockDim.x)
        xs4[i] = ((const float4*)x)[((size_t)b * NN + r0 + (i >> 5)) * 32 + (i & 31)];
    __syncthreads();
    float acc[32];
    #pragma unroll
    for (int r = 0; r < 32; r++) acc[r] = 0.f;
    for (int f4 = 0; f4 < 32; f4++) {
        float l0 = g_lwm[(b * HID + 4 * f4 + 0) * HID + h];
        float l1 = g_lwm[(b * HID + 4 * f4 + 1) * HID + h];
        float l2 = g_lwm[(b * HID + 4 * f4 + 2) * HID + h];
        float l3 = g_lwm[(b * HID + 4 * f4 + 3) * HID + h];
        #pragma unroll
        for (int r = 0; r < 32; r++) {
            float4 xv = xs4[r * 32 + f4];
            acc[r] += xv.x * l0 + xv.y * l1 + xv.z * l2 + xv.w * l3;
        }
    }
    for (int r = 0; r < 32; r++)
        g_xws[((size_t)b * NN + r0 + r) * HID + h] = g_dinv[b * NN + r0 + r] * acc[r];
}

// ---------------- sparse aggregate + sigmoid (one warp per output row) ----------------
__global__ void k_gather(const float* __restrict__ A, float* __restrict__ out) {
    int warp = (blockIdx.x * blockDim.x + threadIdx.x) >> 5;
    int lane = threadIdx.x & 31;
    int b = warp >> 12, i = warp & 4095;
    const float4* xw4 = (const float4*)g_xws + (size_t)b * NN * 32;
    float4 acc = xw4[(size_t)i * 32 + lane];   // +I (diagonal) term: xw_s[i]
    int cnt = g_cnt[warp];
    if (cnt <= CAP) {
        const unsigned short* idx = g_idx + (size_t)warp * CAP;
        int p = 0;
        while (p < cnt) {
            int jv = (p + lane < cnt) ? (int)idx[p + lane] : 0;
            int np = min(32, cnt - p);
            for (int q = 0; q < np; q++) {
                int j = __shfl_sync(0xffffffffu, jv, q);
                float4 v = xw4[(size_t)j * 32 + lane];
                acc.x += v.x; acc.y += v.y; acc.z += v.z; acc.w += v.w;
            }
            p += 32;
        }
    } else {   // overflow fallback: rescan dense row (binary A)
        const float* Ar = A + (size_t)warp * NN;
        for (int j0 = 0; j0 < NN; j0 += 32) {
            float a = Ar[j0 + lane];
            unsigned m = __ballot_sync(0xffffffffu, a != 0.f);
            while (m) {
                int q = __ffs(m) - 1; m &= m - 1;
                float4 v = xw4[(size_t)(j0 + q) * 32 + lane];
                acc.x += v.x; acc.y += v.y; acc.z += v.z; acc.w += v.w;
            }
        }
    }
    float di = g_dinv[warp];
    float4 o4;
    o4.x = sigf(di * acc.x);
    o4.y = sigf(di * acc.y);
    o4.z = sigf(di * acc.z);
    o4.w = sigf(di * acc.w);
    ((float4*)out)[(size_t)warp * 32 + lane] = o4;
}

// ---------------- launch ----------------
extern "C" void kernel_launch(void* const* d_in, const int* in_sizes, int n_in,
                              void* d_out, int out_size) {
    const float* x   = (const float*)d_in[0];
    const float* A   = (const float*)d_in[1];
    const float* cw  = (const float*)d_in[2];
    const float* cb  = (const float*)d_in[3];
    const float* wih = (const float*)d_in[4];
    const float* whh = (const float*)d_in[5];
    const float* bih = (const float*)d_in[6];
    const float* bhh = (const float*)d_in[7];
    float* out = (float*)d_out;

    cudaFuncSetAttribute(k_lstm, cudaFuncAttributeMaxDynamicSharedMemorySize, 131072);

    k_rowsum<<<BATCH * NN / 8, 256>>>(A);
    k_conv<<<BATCH * HID, HID>>>(x, cw, cb);
    k_zx<<<16, 512>>>(wih, bih, bhh);
    k_lstm<<<BATCH, 512, 131072>>>(whh);
    k_xw<<<BATCH * (NN / 32), HID>>>(x);
    k_gather<<<BATCH * NN / 8, 256>>>(A, out);
}

// round 4
// speedup vs baseline: 1.0995x; 1.0995x over previous
#include <cuda_runtime.h>
#include <math.h>

#define BATCH 4
#define NN 4096
#define HID 128
#define G4 512
#define CAP 640

typedef unsigned long long ull;

// ---------------- device scratch ----------------
__device__ float g_dinv[BATCH * NN];
__device__ int   g_cnt[BATCH * NN];
__device__ unsigned short g_idx[(size_t)BATCH * NN * CAP];   // ~21 MB
__device__ float g_dyn[BATCH * HID * HID];                   // conv out [b][time][feat]
__device__ float g_zx[BATCH * HID * G4];                     // x-part of gates + biases
__device__ float g_lwm[BATCH * HID * HID];                   // lstm hidden [b][t][h]
__device__ float g_xws[(size_t)BATCH * NN * HID];            // d_inv[j] * (x @ lw)[j,:]

__device__ __forceinline__ float sigf(float x) {
    return __fdividef(1.f, 1.f + __expf(-x));
}
__device__ __forceinline__ float tanh_fast(float x) {
    float e = __expf(2.f * x);
    return 1.f - __fdividef(2.f, e + 1.f);
}
__device__ __forceinline__ void fma2(ull& d, ull a, ull b) {
    asm("fma.rn.f32x2 %0, %1, %2, %0;" : "+l"(d) : "l"(a), "l"(b));
}
__device__ __forceinline__ float2 unpk(ull v) {
    float2 r; asm("mov.b64 {%0,%1}, %2;" : "=f"(r.x), "=f"(r.y) : "l"(v)); return r;
}
__device__ __forceinline__ ull pk(float x, float y) {
    ull r; asm("mov.b64 %0, {%1,%2};" : "=l"(r) : "f"(x), "f"(y)); return r;
}

// ---------------- pass 1: degree + sparse index build (one warp per row) ----------------
__global__ void k_rowsum(const float* __restrict__ A) {
    int warp = (blockIdx.x * blockDim.x + threadIdx.x) >> 5;
    int lane = threadIdx.x & 31;
    const float4* Ar = (const float4*)(A + (size_t)warp * NN);
    unsigned short* idx = g_idx + (size_t)warp * CAP;
    unsigned lt = (1u << lane) - 1u;
    float s = 0.f;
    int base = 0;
    for (int k = 0; k < NN / 128; k++) {
        float4 a = Ar[k * 32 + lane];
        s += (a.x + a.y) + (a.z + a.w);
        int col = (k * 32 + lane) * 4;
        unsigned m;
        m = __ballot_sync(0xffffffffu, a.x != 0.f);
        if (a.x != 0.f) { int p = base + __popc(m & lt); if (p < CAP) idx[p] = (unsigned short)col; }
        base += __popc(m);
        m = __ballot_sync(0xffffffffu, a.y != 0.f);
        if (a.y != 0.f) { int p = base + __popc(m & lt); if (p < CAP) idx[p] = (unsigned short)(col + 1); }
        base += __popc(m);
        m = __ballot_sync(0xffffffffu, a.z != 0.f);
        if (a.z != 0.f) { int p = base + __popc(m & lt); if (p < CAP) idx[p] = (unsigned short)(col + 2); }
        base += __popc(m);
        m = __ballot_sync(0xffffffffu, a.w != 0.f);
        if (a.w != 0.f) { int p = base + __popc(m & lt); if (p < CAP) idx[p] = (unsigned short)(col + 3); }
        base += __popc(m);
    }
    #pragma unroll
    for (int o = 16; o; o >>= 1) s += __shfl_xor_sync(0xffffffffu, s, o);
    if (lane == 0) { g_cnt[warp] = base; g_dinv[warp] = rsqrtf(s + 1.f); }
}

// ---------------- conv1d (NCH, pad 1): dyn[b][o][t] ----------------
__global__ void k_conv(const float* __restrict__ x, const float* __restrict__ cw,
                       const float* __restrict__ cb) {
    int b = blockIdx.x >> 7, o = blockIdx.x & 127, t = threadIdx.x;
    __shared__ float w[HID * 3];
    for (int i = threadIdx.x; i < HID * 3; i += blockDim.x) w[i] = cw[o * HID * 3 + i];
    __syncthreads();
    float acc = cb[o];
    const float* xb = x + ((size_t)b * NN + (NN - HID)) * HID;
    for (int i = 0; i < HID; i++) {
        const float* xr = xb + i * HID;
        float xm = (t > 0) ? xr[t - 1] : 0.f;
        float x0 = xr[t];
        float xp = (t < HID - 1) ? xr[t + 1] : 0.f;
        acc += xm * w[i * 3] + x0 * w[i * 3 + 1] + xp * w[i * 3 + 2];
    }
    g_dyn[(b * HID + o) * HID + t] = acc;
}

// ---------------- zx[b][t][g] = dyn[b][t] @ w_ih^T + b_ih + b_hh ----------------
__global__ void k_zx(const float* __restrict__ wih, const float* __restrict__ bih,
                     const float* __restrict__ bhh) {
    int b = blockIdx.x >> 2;
    int t0 = (blockIdx.x & 3) * 32;
    int g = threadIdx.x;
    __shared__ float4 dsh[32 * 32];   // [tt][f4]
    for (int i = threadIdx.x; i < 32 * 32; i += blockDim.x)
        dsh[i] = ((const float4*)g_dyn)[(b * HID + t0 + (i >> 5)) * 32 + (i & 31)];
    __syncthreads();
    float acc[32];
    #pragma unroll
    for (int tt = 0; tt < 32; tt++) acc[tt] = 0.f;
    const float4* w4 = (const float4*)wih + g * 32;
    for (int c = 0; c < 4; c++) {
        float4 wv[8];
        #pragma unroll
        for (int j = 0; j < 8; j++) wv[j] = w4[c * 8 + j];
        #pragma unroll
        for (int tt = 0; tt < 32; tt++) {
            float s = 0.f;
            #pragma unroll
            for (int j = 0; j < 8; j++) {
                float4 dv = dsh[tt * 32 + c * 8 + j];
                s += wv[j].x * dv.x + wv[j].y * dv.y + wv[j].z * dv.z + wv[j].w * dv.w;
            }
            acc[tt] += s;
        }
    }
    float bias = bih[g] + bhh[g];
    for (int tt = 0; tt < 32; tt++) g_zx[(b * HID + t0 + tt) * G4 + g] = acc[tt] + bias;
}

// ---------------- LSTM recurrence: one CTA per batch, f32x2 + register weights ----------------
// thread g computes gate g. w_hh[g][0:96] in 48 ull regs, w_hh[g][96:128] in smem.
__global__ void __launch_bounds__(512, 1) k_lstm(const float* __restrict__ whh) {
    int b = blockIdx.x, g = threadIdx.x;
    extern __shared__ ulonglong2 wsv[];       // [8][512]: cols 96+4j..96+4j+3 of gate
    __shared__ float hsh[HID];
    __shared__ float zsh[G4];
    const float4* w4 = (const float4*)whh;

    ull wreg[48];
    #pragma unroll
    for (int j = 0; j < 24; j++) {
        float4 v = w4[(size_t)g * 32 + j];
        wreg[2 * j]     = pk(v.x, v.y);
        wreg[2 * j + 1] = pk(v.z, v.w);
    }
    for (int i = threadIdx.x; i < 8 * 512; i += 512) {
        int k4 = i >> 9, gg = i & 511;
        float4 v = w4[(size_t)gg * 32 + 24 + k4];
        ulonglong2 u;
        u.x = pk(v.x, v.y);
        u.y = pk(v.z, v.w);
        wsv[i] = u;
    }
    if (g < HID) hsh[g] = 0.f;
    float c = 0.f;
    __syncthreads();

    const float* zxb = g_zx + b * HID * G4 + g;
    for (int t = 0; t < HID; t++) {
        float z0 = zxb[t * G4];
        const ulonglong2* h2 = (const ulonglong2*)hsh;    // 32 entries of 2x f32x2
        ull a0 = 0, a1 = 0, a2 = 0, a3 = 0;
        #pragma unroll
        for (int j = 0; j < 24; j++) {
            ulonglong2 hv = h2[j];
            fma2(a0, wreg[2 * j], hv.x);
            fma2(a1, wreg[2 * j + 1], hv.y);
        }
        #pragma unroll
        for (int j = 0; j < 8; j++) {
            ulonglong2 hv = h2[24 + j];
            ulonglong2 wv = wsv[j * 512 + g];
            fma2(a2, wv.x, hv.x);
            fma2(a3, wv.y, hv.y);
        }
        float2 f0 = unpk(a0), f1 = unpk(a1), f2 = unpk(a2), f3 = unpk(a3);
        zsh[g] = z0 + ((f0.x + f0.y) + (f1.x + f1.y)) + ((f2.x + f2.y) + (f3.x + f3.y));
        __syncthreads();
        if (g < HID) {
            float iv = sigf(zsh[g]);
            float fv = sigf(zsh[HID + g]);
            float gv = tanh_fast(zsh[2 * HID + g]);
            float ov = sigf(zsh[3 * HID + g]);
            c = fv * c + iv * gv;
            float h = ov * tanh_fast(c);
            hsh[g] = h;
            g_lwm[(b * HID + t) * HID + g] = h;
        }
        __syncthreads();
    }
}

// ---------------- xw_s[b][j][h] = d_inv[j] * (x[b][j] @ lw[b]) ----------------
__global__ void k_xw(const float* __restrict__ x) {
    int b = blockIdx.x >> 7;
    int r0 = (blockIdx.x & 127) * 32;
    int h = threadIdx.x;
    __shared__ float4 xs4[32 * 32];     // [r][f4]
    for (int i = threadIdx.x; i < 32 * 32; i += blockDim.x)
        xs4[i] = ((const float4*)x)[((size_t)b * NN + r0 + (i >> 5)) * 32 + (i & 31)];
    __syncthreads();
    float acc[32];
    #pragma unroll
    for (int r = 0; r < 32; r++) acc[r] = 0.f;
    for (int f4 = 0; f4 < 32; f4++) {
        float l0 = g_lwm[(b * HID + 4 * f4 + 0) * HID + h];
        float l1 = g_lwm[(b * HID + 4 * f4 + 1) * HID + h];
        float l2 = g_lwm[(b * HID + 4 * f4 + 2) * HID + h];
        float l3 = g_lwm[(b * HID + 4 * f4 + 3) * HID + h];
        #pragma unroll
        for (int r = 0; r < 32; r++) {
            float4 xv = xs4[r * 32 + f4];
            acc[r] += xv.x * l0 + xv.y * l1 + xv.z * l2 + xv.w * l3;
        }
    }
    for (int r = 0; r < 32; r++)
        g_xws[((size_t)b * NN + r0 + r) * HID + h] = g_dinv[b * NN + r0 + r] * acc[r];
}

// ---------------- sparse aggregate + sigmoid (one warp per output row) ----------------
__global__ void k_gather(const float* __restrict__ A, float* __restrict__ out) {
    int warp = (blockIdx.x * blockDim.x + threadIdx.x) >> 5;
    int lane = threadIdx.x & 31;
    int b = warp >> 12, i = warp & 4095;
    const float4* xw4 = (const float4*)g_xws + (size_t)b * NN * 32;
    float4 acc = xw4[(size_t)i * 32 + lane];   // +I (diagonal) term
    int cnt = g_cnt[warp];
    if (cnt <= CAP) {
        const unsigned short* idx = g_idx + (size_t)warp * CAP;
        int p = 0;
        while (p < cnt) {
            int jv = (p + lane < cnt) ? (int)idx[p + lane] : 0;
            int np = min(32, cnt - p);
            for (int q = 0; q < np; q++) {
                int j = __shfl_sync(0xffffffffu, jv, q);
                float4 v = xw4[(size_t)j * 32 + lane];
                acc.x += v.x; acc.y += v.y; acc.z += v.z; acc.w += v.w;
            }
            p += 32;
        }
    } else {
        const float* Ar = A + (size_t)warp * NN;
        for (int j0 = 0; j0 < NN; j0 += 32) {
            float a = Ar[j0 + lane];
            unsigned m = __ballot_sync(0xffffffffu, a != 0.f);
            while (m) {
                int q = __ffs(m) - 1; m &= m - 1;
                float4 v = xw4[(size_t)(j0 + q) * 32 + lane];
                acc.x += v.x; acc.y += v.y; acc.z += v.z; acc.w += v.w;
            }
        }
    }
    float di = g_dinv[warp];
    float4 o4;
    o4.x = sigf(di * acc.x);
    o4.y = sigf(di * acc.y);
    o4.z = sigf(di * acc.z);
    o4.w = sigf(di * acc.w);
    ((float4*)out)[(size_t)warp * 32 + lane] = o4;
}

// ---------------- launch ----------------
extern "C" void kernel_launch(void* const* d_in, const int* in_sizes, int n_in,
                              void* d_out, int out_size) {
    const float* x   = (const float*)d_in[0];
    const float* A   = (const float*)d_in[1];
    const float* cw  = (const float*)d_in[2];
    const float* cb  = (const float*)d_in[3];
    const float* wih = (const float*)d_in[4];
    const float* whh = (const float*)d_in[5];
    const float* bih = (const float*)d_in[6];
    const float* bhh = (const float*)d_in[7];
    float* out = (float*)d_out;

    cudaFuncSetAttribute(k_lstm, cudaFuncAttributeMaxDynamicSharedMemorySize, 65536);

    k_conv<<<BATCH * HID, HID>>>(x, cw, cb);
    k_zx<<<16, 512>>>(wih, bih, bhh);
    k_lstm<<<BATCH, 512, 65536>>>(whh);
    k_rowsum<<<BATCH * NN / 8, 256>>>(A);
    k_xw<<<BATCH * (NN / 32), HID>>>(x);
    k_gather<<<BATCH * NN / 8, 256>>>(A, out);
}

// round 5
// speedup vs baseline: 1.1740x; 1.0677x over previous
#include <cuda_runtime.h>
#include <math.h>
#include <stdint.h>

#define BATCH 4
#define NN 4096
#define HID 128
#define G4 512
#define CAP 640

typedef unsigned long long ull;

// ---------------- device scratch ----------------
__device__ float g_dinv[BATCH * NN];
__device__ int   g_cnt[BATCH * NN];
__device__ unsigned short g_idx[(size_t)BATCH * NN * CAP];   // ~21 MB
__device__ float g_dyn[BATCH * HID * HID];                   // conv out [b][time][feat]
__device__ float g_zx[BATCH * HID * G4];                     // x-part of gates + biases
__device__ float g_lwm[BATCH * HID * HID];                   // lstm hidden [b][t][h]
__device__ float g_xws[(size_t)BATCH * NN * HID];            // d_inv[j] * (x @ lw)[j,:]

__device__ __forceinline__ float sigf(float x) {
    return __fdividef(1.f, 1.f + __expf(-x));
}
__device__ __forceinline__ float tanh_fast(float x) {
    float e = __expf(2.f * x);
    return 1.f - __fdividef(2.f, e + 1.f);
}
__device__ __forceinline__ void fma2(ull& d, ull a, ull b) {
    asm("fma.rn.f32x2 %0, %1, %2, %0;" : "+l"(d) : "l"(a), "l"(b));
}
__device__ __forceinline__ float2 unpk(ull v) {
    float2 r; asm("mov.b64 {%0,%1}, %2;" : "=f"(r.x), "=f"(r.y) : "l"(v)); return r;
}
__device__ __forceinline__ ull pk(float x, float y) {
    ull r; asm("mov.b64 %0, {%1,%2};" : "=l"(r) : "f"(x), "f"(y)); return r;
}

// ---------------- pass 1: degree + sparse index build (one warp per row) ----------------
__global__ void k_rowsum(const float* __restrict__ A) {
    int warp = (blockIdx.x * blockDim.x + threadIdx.x) >> 5;
    int lane = threadIdx.x & 31;
    const float4* Ar = (const float4*)(A + (size_t)warp * NN);
    unsigned short* idx = g_idx + (size_t)warp * CAP;
    unsigned lt = (1u << lane) - 1u;
    float s = 0.f;
    int base = 0;
    for (int k = 0; k < NN / 128; k++) {
        float4 a = Ar[k * 32 + lane];
        s += (a.x + a.y) + (a.z + a.w);
        bool any = (a.x != 0.f) | (a.y != 0.f) | (a.z != 0.f) | (a.w != 0.f);
        if (__ballot_sync(0xffffffffu, any) == 0u) continue;
        int col = (k * 32 + lane) * 4;
        unsigned m;
        m = __ballot_sync(0xffffffffu, a.x != 0.f);
        if (a.x != 0.f) { int p = base + __popc(m & lt); if (p < CAP) idx[p] = (unsigned short)col; }
        base += __popc(m);
        m = __ballot_sync(0xffffffffu, a.y != 0.f);
        if (a.y != 0.f) { int p = base + __popc(m & lt); if (p < CAP) idx[p] = (unsigned short)(col + 1); }
        base += __popc(m);
        m = __ballot_sync(0xffffffffu, a.z != 0.f);
        if (a.z != 0.f) { int p = base + __popc(m & lt); if (p < CAP) idx[p] = (unsigned short)(col + 2); }
        base += __popc(m);
        m = __ballot_sync(0xffffffffu, a.w != 0.f);
        if (a.w != 0.f) { int p = base + __popc(m & lt); if (p < CAP) idx[p] = (unsigned short)(col + 3); }
        base += __popc(m);
    }
    #pragma unroll
    for (int o = 16; o; o >>= 1) s += __shfl_xor_sync(0xffffffffu, s, o);
    if (lane == 0) { g_cnt[warp] = base; g_dinv[warp] = rsqrtf(s + 1.f); }
}

// ---------------- conv1d (NCH, pad 1): dyn[b][o][t] ----------------
__global__ void k_conv(const float* __restrict__ x, const float* __restrict__ cw,
                       const float* __restrict__ cb) {
    int b = blockIdx.x >> 7, o = blockIdx.x & 127, t = threadIdx.x;
    __shared__ float w[HID * 3];
    for (int i = threadIdx.x; i < HID * 3; i += blockDim.x) w[i] = cw[o * HID * 3 + i];
    __syncthreads();
    float acc = cb[o];
    const float* xb = x + ((size_t)b * NN + (NN - HID)) * HID;
    for (int i = 0; i < HID; i++) {
        const float* xr = xb + i * HID;
        float xm = (t > 0) ? xr[t - 1] : 0.f;
        float x0 = xr[t];
        float xp = (t < HID - 1) ? xr[t + 1] : 0.f;
        acc += xm * w[i * 3] + x0 * w[i * 3 + 1] + xp * w[i * 3 + 2];
    }
    g_dyn[(b * HID + o) * HID + t] = acc;
}

// ---------------- zx[b][t][g] = dyn[b][t] @ w_ih^T + b_ih + b_hh ----------------
__global__ void k_zx(const float* __restrict__ wih, const float* __restrict__ bih,
                     const float* __restrict__ bhh) {
    int b = blockIdx.x >> 2;
    int t0 = (blockIdx.x & 3) * 32;
    int g = threadIdx.x;
    __shared__ float4 dsh[32 * 32];   // [tt][f4]
    for (int i = threadIdx.x; i < 32 * 32; i += blockDim.x)
        dsh[i] = ((const float4*)g_dyn)[(b * HID + t0 + (i >> 5)) * 32 + (i & 31)];
    __syncthreads();
    float acc[32];
    #pragma unroll
    for (int tt = 0; tt < 32; tt++) acc[tt] = 0.f;
    const float4* w4 = (const float4*)wih + g * 32;
    for (int c = 0; c < 4; c++) {
        float4 wv[8];
        #pragma unroll
        for (int j = 0; j < 8; j++) wv[j] = w4[c * 8 + j];
        #pragma unroll
        for (int tt = 0; tt < 32; tt++) {
            float s = 0.f;
            #pragma unroll
            for (int j = 0; j < 8; j++) {
                float4 dv = dsh[tt * 32 + c * 8 + j];
                s += wv[j].x * dv.x + wv[j].y * dv.y + wv[j].z * dv.z + wv[j].w * dv.w;
            }
            acc[tt] += s;
        }
    }
    float bias = bih[g] + bhh[g];
    for (int tt = 0; tt < 32; tt++) g_zx[(b * HID + t0 + tt) * G4 + g] = acc[tt] + bias;
}

// ---------------- LSTM: 2-CTA cluster per batch, all weights in registers ----------------
// CTA rank r owns hidden units [64r, 64r+64) => gates {g : (g&127) in [64r,64r+64)}.
// Thread layout: lg = tid & 255 (local gate 0..255), hh = tid >> 8 (column half).
// Warps 0-7 read h[0:64], warps 8-15 read h[64:128] -> pure broadcast LDS.
__global__ void __launch_bounds__(512, 1) __cluster_dims__(2, 1, 1)
k_lstm(const float* __restrict__ whh) {
    int b = blockIdx.x >> 1;
    int r = blockIdx.x & 1;
    int tid = threadIdx.x;
    int lg = tid & 255;
    int hh = tid >> 8;
    int cls = lg >> 6;           // 0=i 1=f 2=g 3=o
    int kk = lg & 63;
    int gate = cls * 128 + 64 * r + kk;

    __shared__ float hbuf[2][HID];
    __shared__ float zA[256];
    __shared__ float zB[256];
    __shared__ __align__(8) unsigned long long mbar;

    // 64 weight floats (cols [64*hh, 64*hh+64)) in 32 ull regs
    ull w[32];
    const float4* w4 = (const float4*)whh + (size_t)gate * 32 + hh * 16;
    #pragma unroll
    for (int j = 0; j < 16; j++) {
        float4 v = w4[j];
        w[2 * j]     = pk(v.x, v.y);
        w[2 * j + 1] = pk(v.z, v.w);
    }
    if (tid < HID) { hbuf[0][tid] = 0.f; hbuf[1][tid] = 0.f; }

    uint32_t mbar_addr = (uint32_t)__cvta_generic_to_shared(&mbar);
    if (tid == 0) {
        asm volatile("mbarrier.init.shared.b64 [%0], 64;" :: "r"(mbar_addr) : "memory");
    }
    __syncthreads();
    asm volatile("barrier.cluster.arrive.aligned;" ::: "memory");
    asm volatile("barrier.cluster.wait.aligned;" ::: "memory");

    float c = 0.f;
    const float* zxp = g_zx + (size_t)b * HID * G4 + gate;

    for (int step = 0; step < HID; step++) {
        const ulonglong2* h2 = (const ulonglong2*)(&hbuf[step & 1][hh * 64]);
        ull a0 = 0, a1 = 0, a2 = 0, a3 = 0;
        #pragma unroll
        for (int j = 0; j < 8; j++) {
            ulonglong2 hv0 = h2[2 * j];
            ulonglong2 hv1 = h2[2 * j + 1];
            fma2(a0, w[4 * j],     hv0.x);
            fma2(a1, w[4 * j + 1], hv0.y);
            fma2(a2, w[4 * j + 2], hv1.x);
            fma2(a3, w[4 * j + 3], hv1.y);
        }
        float2 s0 = unpk(a0), s1 = unpk(a1), s2 = unpk(a2), s3 = unpk(a3);
        float z = ((s0.x + s0.y) + (s1.x + s1.y)) + ((s2.x + s2.y) + (s3.x + s3.y));
        if (hh == 0) zA[lg] = z + zxp[step * G4];
        else         zB[lg] = z;
        __syncthreads();                       // partials ready
        if (tid < 64) {                        // epilogue: hidden unit 64r+tid
            float zi = zA[tid]       + zB[tid];
            float zf = zA[64 + tid]  + zB[64 + tid];
            float zg = zA[128 + tid] + zB[128 + tid];
            float zo = zA[192 + tid] + zB[192 + tid];
            float iv = sigf(zi);
            float fv = sigf(zf);
            float gv = tanh_fast(zg);
            float ov = sigf(zo);
            c = fv * c + iv * gv;
            float h = ov * tanh_fast(c);
            int hidx = 64 * r + tid;
            int nxt = (step + 1) & 1;
            hbuf[nxt][hidx] = h;
            // remote store of my h into peer's hbuf
            uint32_t laddr = (uint32_t)__cvta_generic_to_shared(&hbuf[nxt][hidx]);
            uint32_t raddr;
            asm("mapa.shared::cluster.u32 %0, %1, %2;" : "=r"(raddr) : "r"(laddr), "r"(r ^ 1));
            asm volatile("st.shared::cluster.f32 [%0], %1;" :: "r"(raddr), "f"(h) : "memory");
            g_lwm[((size_t)b * HID + step) * HID + hidx] = h;
            // release-arrive on peer's mbarrier (orders my remote store)
            uint32_t rbar;
            asm("mapa.shared::cluster.u32 %0, %1, %2;" : "=r"(rbar) : "r"(mbar_addr), "r"(r ^ 1));
            asm volatile("mbarrier.arrive.release.cluster.shared::cluster.b64 _, [%0];"
                         :: "r"(rbar) : "memory");
        }
        __syncthreads();                       // local h half + zA/zB reads done
        // wait for peer's 64 arrivals (peer half of h present), acquire cluster
        {
            unsigned par = step & 1;
            asm volatile(
                "{\n\t"
                ".reg .pred P;\n\t"
                "WAITLP_%=:\n\t"
                "mbarrier.try_wait.parity.acquire.cluster.shared::cta.b64 P, [%0], %1;\n\t"
                "@!P bra WAITLP_%=;\n\t"
                "}"
                :: "r"(mbar_addr), "r"(par) : "memory");
        }
    }
    asm volatile("barrier.cluster.arrive.aligned;" ::: "memory");
    asm volatile("barrier.cluster.wait.aligned;" ::: "memory");
}

// ---------------- xw_s[b][j][h] = d_inv[j] * (x[b][j] @ lw[b]) ----------------
__global__ void k_xw(const float* __restrict__ x) {
    int b = blockIdx.x >> 7;
    int r0 = (blockIdx.x & 127) * 32;
    int h = threadIdx.x;
    __shared__ float4 xs4[32 * 32];     // [r][f4]
    for (int i = threadIdx.x; i < 32 * 32; i += blockDim.x)
        xs4[i] = ((const float4*)x)[((size_t)b * NN + r0 + (i >> 5)) * 32 + (i & 31)];
    __syncthreads();
    float acc[32];
    #pragma unroll
    for (int r = 0; r < 32; r++) acc[r] = 0.f;
    for (int f4 = 0; f4 < 32; f4++) {
        float l0 = g_lwm[(b * HID + 4 * f4 + 0) * HID + h];
        float l1 = g_lwm[(b * HID + 4 * f4 + 1) * HID + h];
        float l2 = g_lwm[(b * HID + 4 * f4 + 2) * HID + h];
        float l3 = g_lwm[(b * HID + 4 * f4 + 3) * HID + h];
        #pragma unroll
        for (int r = 0; r < 32; r++) {
            float4 xv = xs4[r * 32 + f4];
            acc[r] += xv.x * l0 + xv.y * l1 + xv.z * l2 + xv.w * l3;
        }
    }
    for (int r = 0; r < 32; r++)
        g_xws[((size_t)b * NN + r0 + r) * HID + h] = g_dinv[b * NN + r0 + r] * acc[r];
}

// ---------------- sparse aggregate + sigmoid (one warp per output row) ----------------
__global__ void k_gather(const float* __restrict__ A, float* __restrict__ out) {
    int warp = (blockIdx.x * blockDim.x + threadIdx.x) >> 5;
    int lane = threadIdx.x & 31;
    int b = warp >> 12, i = warp & 4095;
    const float4* xw4 = (const float4*)g_xws + (size_t)b * NN * 32;
    float4 acc = xw4[(size_t)i * 32 + lane];   // +I (diagonal) term
    int cnt = g_cnt[warp];
    if (cnt <= CAP) {
        const unsigned short* idx = g_idx + (size_t)warp * CAP;
        int p = 0;
        while (p < cnt) {
            int jv = (p + lane < cnt) ? (int)idx[p + lane] : 0;
            int np = min(32, cnt - p);
            for (int q = 0; q < np; q++) {
                int j = __shfl_sync(0xffffffffu, jv, q);
                float4 v = xw4[(size_t)j * 32 + lane];
                acc.x += v.x; acc.y += v.y; acc.z += v.z; acc.w += v.w;
            }
            p += 32;
        }
    } else {
        const float* Ar = A + (size_t)warp * NN;
        for (int j0 = 0; j0 < NN; j0 += 32) {
            float a = Ar[j0 + lane];
            unsigned m = __ballot_sync(0xffffffffu, a != 0.f);
            while (m) {
                int q = __ffs(m) - 1; m &= m - 1;
                float4 v = xw4[(size_t)(j0 + q) * 32 + lane];
                acc.x += v.x; acc.y += v.y; acc.z += v.z; acc.w += v.w;
            }
        }
    }
    float di = g_dinv[warp];
    float4 o4;
    o4.x = sigf(di * acc.x);
    o4.y = sigf(di * acc.y);
    o4.z = sigf(di * acc.z);
    o4.w = sigf(di * acc.w);
    ((float4*)out)[(size_t)warp * 32 + lane] = o4;
}

// ---------------- launch: fork rowsum onto a side stream ----------------
extern "C" void kernel_launch(void* const* d_in, const int* in_sizes, int n_in,
                              void* d_out, int out_size) {
    const float* x   = (const float*)d_in[0];
    const float* A   = (const float*)d_in[1];
    const float* cw  = (const float*)d_in[2];
    const float* cb  = (const float*)d_in[3];
    const float* wih = (const float*)d_in[4];
    const float* whh = (const float*)d_in[5];
    const float* bih = (const float*)d_in[6];
    const float* bhh = (const float*)d_in[7];
    float* out = (float*)d_out;

    static cudaStream_t s2 = nullptr;
    static cudaEvent_t eF = nullptr, eJ = nullptr;
    if (!s2) {
        cudaStreamCreateWithFlags(&s2, cudaStreamNonBlocking);
        cudaEventCreateWithFlags(&eF, cudaEventDisableTiming);
        cudaEventCreateWithFlags(&eJ, cudaEventDisableTiming);
    }

    // fork: rowsum (whole-chip, DRAM-bound) runs beside the LSTM chain
    cudaEventRecord(eF, 0);
    cudaStreamWaitEvent(s2, eF, 0);
    k_rowsum<<<BATCH * NN / 8, 256, 0, s2>>>(A);
    cudaEventRecord(eJ, s2);

    k_conv<<<BATCH * HID, HID>>>(x, cw, cb);
    k_zx<<<16, 512>>>(wih, bih, bhh);
    k_lstm<<<2 * BATCH, 512>>>(whh);

    cudaStreamWaitEvent(0, eJ, 0);
    k_xw<<<BATCH * (NN / 32), HID>>>(x);
    k_gather<<<BATCH * NN / 8, 256>>>(A, out);
}

// round 6
// speedup vs baseline: 1.1829x; 1.0076x over previous
#include <cuda_runtime.h>
#include <math.h>
#include <stdint.h>

#define BATCH 4
#define NN 4096
#define HID 128
#define G4 512
#define CAP 640

typedef unsigned long long ull;

// ---------------- device scratch ----------------
__device__ float g_dinv[BATCH * NN];
__device__ int   g_cnt[BATCH * NN];
__device__ unsigned short g_idx[(size_t)BATCH * NN * CAP];   // ~21 MB
__device__ float g_dyn[BATCH * HID * HID];                   // conv out [b][time][feat]
__device__ float g_zx[BATCH * HID * G4];                     // x-part of gates + biases
__device__ float g_lwm[BATCH * HID * HID];                   // lstm hidden [b][t][h]
__device__ float g_xws[(size_t)BATCH * NN * HID];            // d_inv[j] * (x @ lw)[j,:]

__device__ __forceinline__ float sigf(float x) {
    return __fdividef(1.f, 1.f + __expf(-x));
}
__device__ __forceinline__ float tanh_fast(float x) {
    float e = __expf(2.f * x);
    return 1.f - __fdividef(2.f, e + 1.f);
}
__device__ __forceinline__ void fma2(ull& d, ull a, ull b) {
    asm("fma.rn.f32x2 %0, %1, %2, %0;" : "+l"(d) : "l"(a), "l"(b));
}
__device__ __forceinline__ float2 unpk(ull v) {
    float2 r; asm("mov.b64 {%0,%1}, %2;" : "=f"(r.x), "=f"(r.y) : "l"(v)); return r;
}
__device__ __forceinline__ ull pk(float x, float y) {
    ull r; asm("mov.b64 %0, {%1,%2};" : "=l"(r) : "f"(x), "f"(y)); return r;
}

// ---------------- pass 1: degree + sparse index build (one warp per row) ----------------
__global__ void k_rowsum(const float* __restrict__ A) {
    int warp = (blockIdx.x * blockDim.x + threadIdx.x) >> 5;
    int lane = threadIdx.x & 31;
    const float4* Ar = (const float4*)(A + (size_t)warp * NN);
    unsigned short* idx = g_idx + (size_t)warp * CAP;
    unsigned lt = (1u << lane) - 1u;
    float s = 0.f;
    int base = 0;
    for (int k = 0; k < NN / 128; k++) {
        float4 a = Ar[k * 32 + lane];
        s += (a.x + a.y) + (a.z + a.w);
        bool any = (a.x != 0.f) | (a.y != 0.f) | (a.z != 0.f) | (a.w != 0.f);
        if (__ballot_sync(0xffffffffu, any) == 0u) continue;
        int col = (k * 32 + lane) * 4;
        unsigned m;
        m = __ballot_sync(0xffffffffu, a.x != 0.f);
        if (a.x != 0.f) { int p = base + __popc(m & lt); if (p < CAP) idx[p] = (unsigned short)col; }
        base += __popc(m);
        m = __ballot_sync(0xffffffffu, a.y != 0.f);
        if (a.y != 0.f) { int p = base + __popc(m & lt); if (p < CAP) idx[p] = (unsigned short)(col + 1); }
        base += __popc(m);
        m = __ballot_sync(0xffffffffu, a.z != 0.f);
        if (a.z != 0.f) { int p = base + __popc(m & lt); if (p < CAP) idx[p] = (unsigned short)(col + 2); }
        base += __popc(m);
        m = __ballot_sync(0xffffffffu, a.w != 0.f);
        if (a.w != 0.f) { int p = base + __popc(m & lt); if (p < CAP) idx[p] = (unsigned short)(col + 3); }
        base += __popc(m);
    }
    #pragma unroll
    for (int o = 16; o; o >>= 1) s += __shfl_xor_sync(0xffffffffu, s, o);
    if (lane == 0) { g_cnt[warp] = base; g_dinv[warp] = rsqrtf(s + 1.f); }
}

// ---------------- conv1d (NCH, pad 1): dyn[b][o][t] ----------------
__global__ void k_conv(const float* __restrict__ x, const float* __restrict__ cw,
                       const float* __restrict__ cb) {
    int b = blockIdx.x >> 7, o = blockIdx.x & 127, t = threadIdx.x;
    __shared__ float w[HID * 3];
    for (int i = threadIdx.x; i < HID * 3; i += blockDim.x) w[i] = cw[o * HID * 3 + i];
    __syncthreads();
    float acc = cb[o];
    const float* xb = x + ((size_t)b * NN + (NN - HID)) * HID;
    for (int i = 0; i < HID; i++) {
        const float* xr = xb + i * HID;
        float xm = (t > 0) ? xr[t - 1] : 0.f;
        float x0 = xr[t];
        float xp = (t < HID - 1) ? xr[t + 1] : 0.f;
        acc += xm * w[i * 3] + x0 * w[i * 3 + 1] + xp * w[i * 3 + 2];
    }
    g_dyn[(b * HID + o) * HID + t] = acc;
}

// ---------------- zx[b][t][g] = dyn[b][t] @ w_ih^T + b_ih + b_hh ----------------
__global__ void k_zx(const float* __restrict__ wih, const float* __restrict__ bih,
                     const float* __restrict__ bhh) {
    int b = blockIdx.x >> 2;
    int t0 = (blockIdx.x & 3) * 32;
    int g = threadIdx.x;
    __shared__ float4 dsh[32 * 32];   // [tt][f4]
    for (int i = threadIdx.x; i < 32 * 32; i += blockDim.x)
        dsh[i] = ((const float4*)g_dyn)[(b * HID + t0 + (i >> 5)) * 32 + (i & 31)];
    __syncthreads();
    float acc[32];
    #pragma unroll
    for (int tt = 0; tt < 32; tt++) acc[tt] = 0.f;
    const float4* w4 = (const float4*)wih + g * 32;
    for (int c = 0; c < 4; c++) {
        float4 wv[8];
        #pragma unroll
        for (int j = 0; j < 8; j++) wv[j] = w4[c * 8 + j];
        #pragma unroll
        for (int tt = 0; tt < 32; tt++) {
            float s = 0.f;
            #pragma unroll
            for (int j = 0; j < 8; j++) {
                float4 dv = dsh[tt * 32 + c * 8 + j];
                s += wv[j].x * dv.x + wv[j].y * dv.y + wv[j].z * dv.z + wv[j].w * dv.w;
            }
            acc[tt] += s;
        }
    }
    float bias = bih[g] + bhh[g];
    for (int tt = 0; tt < 32; tt++) g_zx[(b * HID + t0 + tt) * G4 + g] = acc[tt] + bias;
}

// ---------------- LSTM: 2-CTA cluster per batch, weights in registers ----------------
// CTA rank r owns hidden units [64r, 64r+64). Thread: lg = tid&255 (local gate),
// hh = tid>>8 (column half). One mbarrier arrive per step (count=1).
__global__ void __launch_bounds__(512, 1) __cluster_dims__(2, 1, 1)
k_lstm(const float* __restrict__ whh) {
    int b = blockIdx.x >> 1;
    int r = blockIdx.x & 1;
    int tid = threadIdx.x;
    int lg = tid & 255;
    int hh = tid >> 8;
    int cls = lg >> 6;           // 0=i 1=f 2=g 3=o
    int kk = lg & 63;
    int gate = cls * 128 + 64 * r + kk;

    __shared__ float hbuf[2][HID];
    __shared__ float zA[256];
    __shared__ float zB[256];
    __shared__ __align__(8) unsigned long long mbar;

    // 64 weight floats (cols [64*hh, 64*hh+64)) in 32 ull regs
    ull w[32];
    const float4* w4 = (const float4*)whh + (size_t)gate * 32 + hh * 16;
    #pragma unroll
    for (int j = 0; j < 16; j++) {
        float4 v = w4[j];
        w[2 * j]     = pk(v.x, v.y);
        w[2 * j + 1] = pk(v.z, v.w);
    }
    if (tid < HID) { hbuf[0][tid] = 0.f; hbuf[1][tid] = 0.f; }

    uint32_t mbar_addr = (uint32_t)__cvta_generic_to_shared(&mbar);
    if (tid == 0) {
        asm volatile("mbarrier.init.shared.b64 [%0], 1;" :: "r"(mbar_addr) : "memory");
    }
    // precompute remote addresses (peer CTA) for h-forwarding and barrier
    int fw = tid & 15;
    uint32_t lh0 = (uint32_t)__cvta_generic_to_shared(&hbuf[0][64 * r + 4 * fw]);
    uint32_t lh1 = (uint32_t)__cvta_generic_to_shared(&hbuf[1][64 * r + 4 * fw]);
    uint32_t ph0, ph1, rbar;
    asm("mapa.shared::cluster.u32 %0, %1, %2;" : "=r"(ph0) : "r"(lh0), "r"(r ^ 1));
    asm("mapa.shared::cluster.u32 %0, %1, %2;" : "=r"(ph1) : "r"(lh1), "r"(r ^ 1));
    asm("mapa.shared::cluster.u32 %0, %1, %2;" : "=r"(rbar) : "r"(mbar_addr), "r"(r ^ 1));
    __syncthreads();
    asm volatile("barrier.cluster.arrive.aligned;" ::: "memory");
    asm volatile("barrier.cluster.wait.aligned;" ::: "memory");

    float c = 0.f;
    const float* zxp = g_zx + (size_t)b * HID * G4 + gate;
    float z0 = zxp[0];

    for (int step = 0; step < HID; step++) {
        float znext = (step < HID - 1) ? zxp[(step + 1) * G4] : 0.f;
        const ulonglong2* h2 = (const ulonglong2*)(&hbuf[step & 1][hh * 64]);
        ull a0 = 0, a1 = 0, a2 = 0, a3 = 0;
        #pragma unroll
        for (int j = 0; j < 8; j++) {
            ulonglong2 hv0 = h2[2 * j];
            ulonglong2 hv1 = h2[2 * j + 1];
            fma2(a0, w[4 * j],     hv0.x);
            fma2(a1, w[4 * j + 1], hv0.y);
            fma2(a2, w[4 * j + 2], hv1.x);
            fma2(a3, w[4 * j + 3], hv1.y);
        }
        float2 s0 = unpk(a0), s1 = unpk(a1), s2 = unpk(a2), s3 = unpk(a3);
        float z = ((s0.x + s0.y) + (s1.x + s1.y)) + ((s2.x + s2.y) + (s3.x + s3.y));
        if (hh == 0) zA[lg] = z + z0;
        else         zB[lg] = z;
        z0 = znext;
        __syncthreads();                       // partials ready
        int nxt = (step + 1) & 1;
        if (tid < 64) {                        // epilogue: hidden unit 64r+tid
            float zi = zA[tid]       + zB[tid];
            float zf = zA[64 + tid]  + zB[64 + tid];
            float zg = zA[128 + tid] + zB[128 + tid];
            float zo = zA[192 + tid] + zB[192 + tid];
            float iv = sigf(zi);
            float fv = sigf(zf);
            float gv = tanh_fast(zg);
            float ov = sigf(zo);
            c = fv * c + iv * gv;
            float h = ov * tanh_fast(c);
            int hidx = 64 * r + tid;
            hbuf[nxt][hidx] = h;
            g_lwm[((size_t)b * HID + step) * HID + hidx] = h;
        }
        __syncthreads();                       // local h half visible CTA-wide
        if (tid < 16) {                        // forward my half to peer: 16 x st.v4
            const float4* src = (const float4*)&hbuf[nxt][64 * r + 4 * tid];
            float4 v = *src;
            uint32_t dst = nxt ? ph1 : ph0;
            asm volatile("st.shared::cluster.v4.f32 [%0], {%1,%2,%3,%4};"
                         :: "r"(dst), "f"(v.x), "f"(v.y), "f"(v.z), "f"(v.w) : "memory");
            __syncwarp(0x0000FFFFu);
            if (tid == 0) {
                asm volatile("fence.release.cluster;" ::: "memory");
                asm volatile("mbarrier.arrive.shared::cluster.b64 _, [%0];"
                             :: "r"(rbar) : "memory");
            }
        }
        // wait for peer's arrive (peer half of hbuf[nxt] present)
        {
            unsigned par = step & 1;
            asm volatile(
                "{\n\t"
                ".reg .pred P;\n\t"
                "WAITLP_%=:\n\t"
                "mbarrier.try_wait.parity.acquire.cluster.shared::cta.b64 P, [%0], %1;\n\t"
                "@!P bra WAITLP_%=;\n\t"
                "}"
                :: "r"(mbar_addr), "r"(par) : "memory");
        }
    }
    asm volatile("barrier.cluster.arrive.aligned;" ::: "memory");
    asm volatile("barrier.cluster.wait.aligned;" ::: "memory");
}

// ---------------- xw_s[b][j][h] = d_inv[j] * (x[b][j] @ lw[b]) ----------------
__global__ void k_xw(const float* __restrict__ x) {
    int b = blockIdx.x >> 7;
    int r0 = (blockIdx.x & 127) * 32;
    int h = threadIdx.x;
    __shared__ float4 xs4[32 * 32];     // [r][f4]
    for (int i = threadIdx.x; i < 32 * 32; i += blockDim.x)
        xs4[i] = ((const float4*)x)[((size_t)b * NN + r0 + (i >> 5)) * 32 + (i & 31)];
    __syncthreads();
    float acc[32];
    #pragma unroll
    for (int r = 0; r < 32; r++) acc[r] = 0.f;
    for (int f4 = 0; f4 < 32; f4++) {
        float l0 = g_lwm[(b * HID + 4 * f4 + 0) * HID + h];
        float l1 = g_lwm[(b * HID + 4 * f4 + 1) * HID + h];
        float l2 = g_lwm[(b * HID + 4 * f4 + 2) * HID + h];
        float l3 = g_lwm[(b * HID + 4 * f4 + 3) * HID + h];
        #pragma unroll
        for (int r = 0; r < 32; r++) {
            float4 xv = xs4[r * 32 + f4];
            acc[r] += xv.x * l0 + xv.y * l1 + xv.z * l2 + xv.w * l3;
        }
    }
    for (int r = 0; r < 32; r++)
        g_xws[((size_t)b * NN + r0 + r) * HID + h] = g_dinv[b * NN + r0 + r] * acc[r];
}

// ---------------- sparse aggregate + sigmoid (one warp per output row) ----------------
__global__ void k_gather(const float* __restrict__ A, float* __restrict__ out) {
    int warp = (blockIdx.x * blockDim.x + threadIdx.x) >> 5;
    int lane = threadIdx.x & 31;
    int b = warp >> 12, i = warp & 4095;
    const float4* xw4 = (const float4*)g_xws + (size_t)b * NN * 32;
    float4 acc = xw4[(size_t)i * 32 + lane];   // +I (diagonal) term
    int cnt = g_cnt[warp];
    if (cnt <= CAP) {
        const unsigned short* idx = g_idx + (size_t)warp * CAP;
        int p = 0;
        while (p < cnt) {
            int jv = (p + lane < cnt) ? (int)idx[p + lane] : 0;
            int np = min(32, cnt - p);
            int q = 0;
            for (; q + 4 <= np; q += 4) {
                int j0 = __shfl_sync(0xffffffffu, jv, q);
                int j1 = __shfl_sync(0xffffffffu, jv, q + 1);
                int j2 = __shfl_sync(0xffffffffu, jv, q + 2);
                int j3 = __shfl_sync(0xffffffffu, jv, q + 3);
                float4 v0 = xw4[(size_t)j0 * 32 + lane];
                float4 v1 = xw4[(size_t)j1 * 32 + lane];
                float4 v2 = xw4[(size_t)j2 * 32 + lane];
                float4 v3 = xw4[(size_t)j3 * 32 + lane];
                acc.x += (v0.x + v1.x) + (v2.x + v3.x);
                acc.y += (v0.y + v1.y) + (v2.y + v3.y);
                acc.z += (v0.z + v1.z) + (v2.z + v3.z);
                acc.w += (v0.w + v1.w) + (v2.w + v3.w);
            }
            for (; q < np; q++) {
                int j = __shfl_sync(0xffffffffu, jv, q);
                float4 v = xw4[(size_t)j * 32 + lane];
                acc.x += v.x; acc.y += v.y; acc.z += v.z; acc.w += v.w;
            }
            p += 32;
        }
    } else {
        const float* Ar = A + (size_t)warp * NN;
        for (int j0 = 0; j0 < NN; j0 += 32) {
            float a = Ar[j0 + lane];
            unsigned m = __ballot_sync(0xffffffffu, a != 0.f);
            while (m) {
                int q = __ffs(m) - 1; m &= m - 1;
                float4 v = xw4[(size_t)(j0 + q) * 32 + lane];
                acc.x += v.x; acc.y += v.y; acc.z += v.z; acc.w += v.w;
            }
        }
    }
    float di = g_dinv[warp];
    float4 o4;
    o4.x = sigf(di * acc.x);
    o4.y = sigf(di * acc.y);
    o4.z = sigf(di * acc.z);
    o4.w = sigf(di * acc.w);
    ((float4*)out)[(size_t)warp * 32 + lane] = o4;
}

// ---------------- launch: fork rowsum onto a side stream ----------------
extern "C" void kernel_launch(void* const* d_in, const int* in_sizes, int n_in,
                              void* d_out, int out_size) {
    const float* x   = (const float*)d_in[0];
    const float* A   = (const float*)d_in[1];
    const float* cw  = (const float*)d_in[2];
    const float* cb  = (const float*)d_in[3];
    const float* wih = (const float*)d_in[4];
    const float* whh = (const float*)d_in[5];
    const float* bih = (const float*)d_in[6];
    const float* bhh = (const float*)d_in[7];
    float* out = (float*)d_out;

    static cudaStream_t s2 = nullptr;
    static cudaEvent_t eF = nullptr, eJ = nullptr;
    if (!s2) {
        cudaStreamCreateWithFlags(&s2, cudaStreamNonBlocking);
        cudaEventCreateWithFlags(&eF, cudaEventDisableTiming);
        cudaEventCreateWithFlags(&eJ, cudaEventDisableTiming);
    }

    // fork: rowsum (whole-chip, DRAM-bound) runs beside the LSTM chain
    cudaEventRecord(eF, 0);
    cudaStreamWaitEvent(s2, eF, 0);
    k_rowsum<<<BATCH * NN / 8, 256, 0, s2>>>(A);
    cudaEventRecord(eJ, s2);

    k_conv<<<BATCH * HID, HID>>>(x, cw, cb);
    k_zx<<<16, 512>>>(wih, bih, bhh);
    k_lstm<<<2 * BATCH, 512>>>(whh);

    cudaStreamWaitEvent(0, eJ, 0);
    k_xw<<<BATCH * (NN / 32), HID>>>(x);
    k_gather<<<BATCH * NN / 8, 256>>>(A, out);
}

// round 7
// speedup vs baseline: 1.2526x; 1.0589x over previous
#include <cuda_runtime.h>
#include <math.h>
#include <stdint.h>

#define BATCH 4
#define NN 4096
#define HID 128
#define G4 512
#define CAP 640

typedef unsigned long long ull;

// ---------------- device scratch ----------------
__device__ float g_dinv[BATCH * NN];
__device__ int   g_cnt[BATCH * NN];
__device__ unsigned short g_idx[(size_t)BATCH * NN * CAP];   // ~21 MB
__device__ float g_dyn[BATCH * HID * HID];                   // conv out [b][time][feat]
__device__ float g_zx[BATCH * HID * G4];                     // x-part of gates + biases
__device__ float g_lwm[BATCH * HID * HID];                   // lstm hidden [b][t][h]
__device__ float g_xws[(size_t)BATCH * NN * HID];            // d_inv[j] * (x @ lw)[j,:]

__device__ __forceinline__ float sigf(float x) {
    return __fdividef(1.f, 1.f + __expf(-x));
}
__device__ __forceinline__ float tanh_fast(float x) {
    float e = __expf(2.f * x);
    return 1.f - __fdividef(2.f, e + 1.f);
}
__device__ __forceinline__ void fma2(ull& d, ull a, ull b) {
    asm("fma.rn.f32x2 %0, %1, %2, %0;" : "+l"(d) : "l"(a), "l"(b));
}
__device__ __forceinline__ float2 unpk(ull v) {
    float2 r; asm("mov.b64 {%0,%1}, %2;" : "=f"(r.x), "=f"(r.y) : "l"(v)); return r;
}
__device__ __forceinline__ ull pk(float x, float y) {
    ull r; asm("mov.b64 %0, {%1,%2};" : "=l"(r) : "f"(x), "f"(y)); return r;
}

// ---------------- pass 1: degree + sparse index build (one warp per row) ----------------
__global__ void k_rowsum(const float* __restrict__ A) {
    int warp = (blockIdx.x * blockDim.x + threadIdx.x) >> 5;
    int lane = threadIdx.x & 31;
    const float4* Ar = (const float4*)(A + (size_t)warp * NN);
    unsigned short* idx = g_idx + (size_t)warp * CAP;
    unsigned lt = (1u << lane) - 1u;
    float s = 0.f;
    int base = 0;
    for (int k = 0; k < NN / 128; k++) {
        float4 a = Ar[k * 32 + lane];
        s += (a.x + a.y) + (a.z + a.w);
        bool any = (a.x != 0.f) | (a.y != 0.f) | (a.z != 0.f) | (a.w != 0.f);
        if (__ballot_sync(0xffffffffu, any) == 0u) continue;
        int col = (k * 32 + lane) * 4;
        unsigned m;
        m = __ballot_sync(0xffffffffu, a.x != 0.f);
        if (a.x != 0.f) { int p = base + __popc(m & lt); if (p < CAP) idx[p] = (unsigned short)col; }
        base += __popc(m);
        m = __ballot_sync(0xffffffffu, a.y != 0.f);
        if (a.y != 0.f) { int p = base + __popc(m & lt); if (p < CAP) idx[p] = (unsigned short)(col + 1); }
        base += __popc(m);
        m = __ballot_sync(0xffffffffu, a.z != 0.f);
        if (a.z != 0.f) { int p = base + __popc(m & lt); if (p < CAP) idx[p] = (unsigned short)(col + 2); }
        base += __popc(m);
        m = __ballot_sync(0xffffffffu, a.w != 0.f);
        if (a.w != 0.f) { int p = base + __popc(m & lt); if (p < CAP) idx[p] = (unsigned short)(col + 3); }
        base += __popc(m);
    }
    #pragma unroll
    for (int o = 16; o; o >>= 1) s += __shfl_xor_sync(0xffffffffu, s, o);
    if (lane == 0) { g_cnt[warp] = base; g_dinv[warp] = rsqrtf(s + 1.f); }
}

// ---------------- conv1d (NCH, pad 1): dyn[b][o][t] ----------------
__global__ void k_conv(const float* __restrict__ x, const float* __restrict__ cw,
                       const float* __restrict__ cb) {
    int b = blockIdx.x >> 7, o = blockIdx.x & 127, t = threadIdx.x;
    __shared__ float w[HID * 3];
    for (int i = threadIdx.x; i < HID * 3; i += blockDim.x) w[i] = cw[o * HID * 3 + i];
    __syncthreads();
    float acc = cb[o];
    const float* xb = x + ((size_t)b * NN + (NN - HID)) * HID;
    for (int i = 0; i < HID; i++) {
        const float* xr = xb + i * HID;
        float xm = (t > 0) ? xr[t - 1] : 0.f;
        float x0 = xr[t];
        float xp = (t < HID - 1) ? xr[t + 1] : 0.f;
        acc += xm * w[i * 3] + x0 * w[i * 3 + 1] + xp * w[i * 3 + 2];
    }
    g_dyn[(b * HID + o) * HID + t] = acc;
}

// ---------------- zx[b][t][g] = dyn[b][t] @ w_ih^T + b_ih + b_hh ----------------
__global__ void k_zx(const float* __restrict__ wih, const float* __restrict__ bih,
                     const float* __restrict__ bhh) {
    int b = blockIdx.x >> 2;
    int t0 = (blockIdx.x & 3) * 32;
    int g = threadIdx.x;
    __shared__ float4 dsh[32 * 32];   // [tt][f4]
    for (int i = threadIdx.x; i < 32 * 32; i += blockDim.x)
        dsh[i] = ((const float4*)g_dyn)[(b * HID + t0 + (i >> 5)) * 32 + (i & 31)];
    __syncthreads();
    float acc[32];
    #pragma unroll
    for (int tt = 0; tt < 32; tt++) acc[tt] = 0.f;
    const float4* w4 = (const float4*)wih + g * 32;
    for (int c = 0; c < 4; c++) {
        float4 wv[8];
        #pragma unroll
        for (int j = 0; j < 8; j++) wv[j] = w4[c * 8 + j];
        #pragma unroll
        for (int tt = 0; tt < 32; tt++) {
            float s = 0.f;
            #pragma unroll
            for (int j = 0; j < 8; j++) {
                float4 dv = dsh[tt * 32 + c * 8 + j];
                s += wv[j].x * dv.x + wv[j].y * dv.y + wv[j].z * dv.z + wv[j].w * dv.w;
            }
            acc[tt] += s;
        }
    }
    float bias = bih[g] + bhh[g];
    for (int tt = 0; tt < 32; tt++) g_zx[(b * HID + t0 + tt) * G4 + g] = acc[tt] + bias;
}

// ---------------- LSTM: 2-CTA cluster per batch, weights in registers ----------------
// CTA rank r owns hidden units [64r, 64r+64). Exchange via plain DSMEM stores +
// release/acquire flag counters (no mbarrier, no cluster fence). Only warps that
// read the PEER half (hh != r) spin, so DSMEM latency overlaps local-half FMA.
__global__ void __launch_bounds__(512, 1) __cluster_dims__(2, 1, 1)
k_lstm(const float* __restrict__ whh) {
    int b = blockIdx.x >> 1;
    int r = blockIdx.x & 1;
    int tid = threadIdx.x;
    int lg = tid & 255;
    int hh = tid >> 8;
    int cls = lg >> 6;           // 0=i 1=f 2=g 3=o
    int kk = lg & 63;
    int gate = cls * 128 + 64 * r + kk;

    __shared__ float hbuf[2][HID];
    __shared__ float zA[256];
    __shared__ float zB[256];
    __shared__ __align__(8) unsigned int flg[2][2];   // [parity][epi-warp]

    // 64 weight floats (cols [64*hh, 64*hh+64)) in 32 ull regs
    ull w[32];
    const float4* w4 = (const float4*)whh + (size_t)gate * 32 + hh * 16;
    #pragma unroll
    for (int j = 0; j < 16; j++) {
        float4 v = w4[j];
        w[2 * j]     = pk(v.x, v.y);
        w[2 * j + 1] = pk(v.z, v.w);
    }
    if (tid < HID) { hbuf[0][tid] = 0.f; hbuf[1][tid] = 0.f; }
    if (tid < 4) ((unsigned int*)flg)[tid] = 0u;

    // local flag-pair addresses (u64 read)
    uint32_t lf0 = (uint32_t)__cvta_generic_to_shared(&flg[0][0]);
    uint32_t lf1 = (uint32_t)__cvta_generic_to_shared(&flg[1][0]);
    // epilogue-thread remote addresses (peer CTA)
    uint32_t ph0 = 0, ph1 = 0, pf0 = 0, pf1 = 0;
    if (tid < 64) {
        int hidx = 64 * r + tid;
        uint32_t a0 = (uint32_t)__cvta_generic_to_shared(&hbuf[0][hidx]);
        uint32_t a1 = (uint32_t)__cvta_generic_to_shared(&hbuf[1][hidx]);
        int wv = tid >> 5;
        uint32_t f0 = (uint32_t)__cvta_generic_to_shared(&flg[0][wv]);
        uint32_t f1 = (uint32_t)__cvta_generic_to_shared(&flg[1][wv]);
        asm("mapa.shared::cluster.u32 %0, %1, %2;" : "=r"(ph0) : "r"(a0), "r"(r ^ 1));
        asm("mapa.shared::cluster.u32 %0, %1, %2;" : "=r"(ph1) : "r"(a1), "r"(r ^ 1));
        asm("mapa.shared::cluster.u32 %0, %1, %2;" : "=r"(pf0) : "r"(f0), "r"(r ^ 1));
        asm("mapa.shared::cluster.u32 %0, %1, %2;" : "=r"(pf1) : "r"(f1), "r"(r ^ 1));
    }
    __syncthreads();
    asm volatile("barrier.cluster.arrive.aligned;" ::: "memory");
    asm volatile("barrier.cluster.wait.aligned;" ::: "memory");

    float c = 0.f;
    const float* zxp = g_zx + (size_t)b * HID * G4 + gate;
    float z0 = zxp[0];
    bool spinner = (hh != r);

    for (int step = 0; step < HID; step++) {
        // wait for peer half of hbuf[cur] (only warps that read it)
        if (spinner) {
            uint32_t fa = (step & 1) ? lf1 : lf0;
            ull v; unsigned lo, hi;
            do {
                asm volatile("ld.acquire.cluster.shared::cta.u64 %0, [%1];"
                             : "=l"(v) : "r"(fa) : "memory");
                lo = (unsigned)v; hi = (unsigned)(v >> 32);
            } while ((int)lo < step || (int)hi < step);
        }
        float znext = (step < HID - 1) ? zxp[(step + 1) * G4] : 0.f;
        const ulonglong2* h2 = (const ulonglong2*)(&hbuf[step & 1][hh * 64]);
        ull a0 = 0, a1 = 0, a2 = 0, a3 = 0;
        #pragma unroll
        for (int j = 0; j < 8; j++) {
            ulonglong2 hv0 = h2[2 * j];
            ulonglong2 hv1 = h2[2 * j + 1];
            fma2(a0, w[4 * j],     hv0.x);
            fma2(a1, w[4 * j + 1], hv0.y);
            fma2(a2, w[4 * j + 2], hv1.x);
            fma2(a3, w[4 * j + 3], hv1.y);
        }
        float2 s0 = unpk(a0), s1 = unpk(a1), s2 = unpk(a2), s3 = unpk(a3);
        float z = ((s0.x + s0.y) + (s1.x + s1.y)) + ((s2.x + s2.y) + (s3.x + s3.y));
        if (hh == 0) zA[lg] = z + z0;
        else         zB[lg] = z;
        z0 = znext;
        __syncthreads();                       // partials ready
        int nxt = (step + 1) & 1;
        if (tid < 64) {                        // epilogue: hidden unit 64r+tid
            float zi = zA[tid]       + zB[tid];
            float zf = zA[64 + tid]  + zB[64 + tid];
            float zg = zA[128 + tid] + zB[128 + tid];
            float zo = zA[192 + tid] + zB[192 + tid];
            float iv = sigf(zi);
            float fv = sigf(zf);
            float gv = tanh_fast(zg);
            float ov = sigf(zo);
            c = fv * c + iv * gv;
            float h = ov * tanh_fast(c);
            int hidx = 64 * r + tid;
            hbuf[nxt][hidx] = h;
            // plain remote store of my h into peer's hbuf[nxt]
            uint32_t pa = nxt ? ph1 : ph0;
            asm volatile("st.shared::cluster.f32 [%0], %1;" :: "r"(pa), "f"(h) : "memory");
            g_lwm[((size_t)b * HID + step) * HID + hidx] = h;
            __syncwarp();
            if ((tid & 31) == 0) {             // one release per epilogue warp
                uint32_t fa = nxt ? pf1 : pf0;
                asm volatile("st.release.cluster.shared::cluster.u32 [%0], %1;"
                             :: "r"(fa), "r"(step + 1) : "memory");
            }
        }
        __syncthreads();                       // local h half + zA/zB reads done
    }
    asm volatile("barrier.cluster.arrive.aligned;" ::: "memory");
    asm volatile("barrier.cluster.wait.aligned;" ::: "memory");
}

// ---------------- xw_s[b][j][h] = d_inv[j] * (x[b][j] @ lw[b]) ----------------
__global__ void k_xw(const float* __restrict__ x) {
    int b = blockIdx.x >> 7;
    int r0 = (blockIdx.x & 127) * 32;
    int h = threadIdx.x;
    __shared__ float4 xs4[32 * 32];     // [r][f4]
    for (int i = threadIdx.x; i < 32 * 32; i += blockDim.x)
        xs4[i] = ((const float4*)x)[((size_t)b * NN + r0 + (i >> 5)) * 32 + (i & 31)];
    __syncthreads();
    float acc[32];
    #pragma unroll
    for (int r = 0; r < 32; r++) acc[r] = 0.f;
    for (int f4 = 0; f4 < 32; f4++) {
        float l0 = g_lwm[(b * HID + 4 * f4 + 0) * HID + h];
        float l1 = g_lwm[(b * HID + 4 * f4 + 1) * HID + h];
        float l2 = g_lwm[(b * HID + 4 * f4 + 2) * HID + h];
        float l3 = g_lwm[(b * HID + 4 * f4 + 3) * HID + h];
        #pragma unroll
        for (int r = 0; r < 32; r++) {
            float4 xv = xs4[r * 32 + f4];
            acc[r] += xv.x * l0 + xv.y * l1 + xv.z * l2 + xv.w * l3;
        }
    }
    for (int r = 0; r < 32; r++)
        g_xws[((size_t)b * NN + r0 + r) * HID + h] = g_dinv[b * NN + r0 + r] * acc[r];
}

// ---------------- sparse aggregate + sigmoid (one warp per output row) ----------------
__global__ void k_gather(const float* __restrict__ A, float* __restrict__ out) {
    int warp = (blockIdx.x * blockDim.x + threadIdx.x) >> 5;
    int lane = threadIdx.x & 31;
    int b = warp >> 12, i = warp & 4095;
    const float4* xw4 = (const float4*)g_xws + (size_t)b * NN * 32;
    float4 acc = xw4[(size_t)i * 32 + lane];   // +I (diagonal) term
    int cnt = g_cnt[warp];
    if (cnt <= CAP) {
        const unsigned short* idx = g_idx + (size_t)warp * CAP;
        int p = 0;
        while (p < cnt) {
            int jv = (p + lane < cnt) ? (int)idx[p + lane] : 0;
            int np = min(32, cnt - p);
            int q = 0;
            for (; q + 4 <= np; q += 4) {
                int j0 = __shfl_sync(0xffffffffu, jv, q);
                int j1 = __shfl_sync(0xffffffffu, jv, q + 1);
                int j2 = __shfl_sync(0xffffffffu, jv, q + 2);
                int j3 = __shfl_sync(0xffffffffu, jv, q + 3);
                float4 v0 = xw4[(size_t)j0 * 32 + lane];
                float4 v1 = xw4[(size_t)j1 * 32 + lane];
                float4 v2 = xw4[(size_t)j2 * 32 + lane];
                float4 v3 = xw4[(size_t)j3 * 32 + lane];
                acc.x += (v0.x + v1.x) + (v2.x + v3.x);
                acc.y += (v0.y + v1.y) + (v2.y + v3.y);
                acc.z += (v0.z + v1.z) + (v2.z + v3.z);
                acc.w += (v0.w + v1.w) + (v2.w + v3.w);
            }
            for (; q < np; q++) {
                int j = __shfl_sync(0xffffffffu, jv, q);
                float4 v = xw4[(size_t)j * 32 + lane];
                acc.x += v.x; acc.y += v.y; acc.z += v.z; acc.w += v.w;
            }
            p += 32;
        }
    } else {
        const float* Ar = A + (size_t)warp * NN;
        for (int j0 = 0; j0 < NN; j0 += 32) {
            float a = Ar[j0 + lane];
            unsigned m = __ballot_sync(0xffffffffu, a != 0.f);
            while (m) {
                int q = __ffs(m) - 1; m &= m - 1;
                float4 v = xw4[(size_t)(j0 + q) * 32 + lane];
                acc.x += v.x; acc.y += v.y; acc.z += v.z; acc.w += v.w;
            }
        }
    }
    float di = g_dinv[warp];
    float4 o4;
    o4.x = sigf(di * acc.x);
    o4.y = sigf(di * acc.y);
    o4.z = sigf(di * acc.z);
    o4.w = sigf(di * acc.w);
    ((float4*)out)[(size_t)warp * 32 + lane] = o4;
}

// ---------------- launch: fork rowsum onto a side stream ----------------
extern "C" void kernel_launch(void* const* d_in, const int* in_sizes, int n_in,
                              void* d_out, int out_size) {
    const float* x   = (const float*)d_in[0];
    const float* A   = (const float*)d_in[1];
    const float* cw  = (const float*)d_in[2];
    const float* cb  = (const float*)d_in[3];
    const float* wih = (const float*)d_in[4];
    const float* whh = (const float*)d_in[5];
    const float* bih = (const float*)d_in[6];
    const float* bhh = (const float*)d_in[7];
    float* out = (float*)d_out;

    static cudaStream_t s2 = nullptr;
    static cudaEvent_t eF = nullptr, eJ = nullptr;
    if (!s2) {
        cudaStreamCreateWithFlags(&s2, cudaStreamNonBlocking);
        cudaEventCreateWithFlags(&eF, cudaEventDisableTiming);
        cudaEventCreateWithFlags(&eJ, cudaEventDisableTiming);
    }

    // fork: rowsum (whole-chip, DRAM-bound) runs beside the LSTM chain
    cudaEventRecord(eF, 0);
    cudaStreamWaitEvent(s2, eF, 0);
    k_rowsum<<<BATCH * NN / 8, 256, 0, s2>>>(A);
    cudaEventRecord(eJ, s2);

    k_conv<<<BATCH * HID, HID>>>(x, cw, cb);
    k_zx<<<16, 512>>>(wih, bih, bhh);
    k_lstm<<<2 * BATCH, 512>>>(whh);

    cudaStreamWaitEvent(0, eJ, 0);
    k_xw<<<BATCH * (NN / 32), HID>>>(x);
    k_gather<<<BATCH * NN / 8, 256>>>(A, out);
}

// round 8
// speedup vs baseline: 1.3353x; 1.0660x over previous
#include <cuda_runtime.h>
#include <math.h>
#include <stdint.h>

#define BATCH 4
#define NN 4096
#define HID 128
#define G4 512
#define CAP 640

typedef unsigned long long ull;

// ---------------- device scratch ----------------
__device__ float g_dinv[BATCH * NN];
__device__ int   g_cnt[BATCH * NN];
__device__ unsigned short g_idx[(size_t)BATCH * NN * CAP];   // ~21 MB
__device__ float g_dyn[BATCH * HID * HID];                   // conv out
__device__ float g_zx[BATCH * HID * G4];                     // x-part of gates + biases
__device__ float g_lwm[BATCH * HID * HID];                   // lstm hidden [b][t][h]
__device__ float g_xs[(size_t)BATCH * NN * HID];             // d_j * x[b][j][:]
__device__ float g_agg[(size_t)BATCH * NN * HID];            // (A_norm @ x)[b][i][:]

__device__ __forceinline__ float sigf(float x) {
    return __fdividef(1.f, 1.f + __expf(-x));
}
__device__ __forceinline__ float tanh_fast(float x) {
    float e = __expf(2.f * x);
    return 1.f - __fdividef(2.f, e + 1.f);
}
__device__ __forceinline__ void fma2(ull& d, ull a, ull b) {
    asm("fma.rn.f32x2 %0, %1, %2, %0;" : "+l"(d) : "l"(a), "l"(b));
}
__device__ __forceinline__ float2 unpk(ull v) {
    float2 r; asm("mov.b64 {%0,%1}, %2;" : "=f"(r.x), "=f"(r.y) : "l"(v)); return r;
}
__device__ __forceinline__ ull pk(float x, float y) {
    ull r; asm("mov.b64 %0, {%1,%2};" : "=l"(r) : "f"(x), "f"(y)); return r;
}

// ---------------- pass 1: degree + sparse index build (one warp per row) ----------------
__global__ void k_rowsum(const float* __restrict__ A) {
    int warp = (blockIdx.x * blockDim.x + threadIdx.x) >> 5;
    int lane = threadIdx.x & 31;
    const float4* Ar = (const float4*)(A + (size_t)warp * NN);
    unsigned short* idx = g_idx + (size_t)warp * CAP;
    unsigned lt = (1u << lane) - 1u;
    float s = 0.f;
    int base = 0;
    for (int k = 0; k < NN / 128; k++) {
        float4 a = Ar[k * 32 + lane];
        s += (a.x + a.y) + (a.z + a.w);
        bool any = (a.x != 0.f) | (a.y != 0.f) | (a.z != 0.f) | (a.w != 0.f);
        if (__ballot_sync(0xffffffffu, any) == 0u) continue;
        int col = (k * 32 + lane) * 4;
        unsigned m;
        m = __ballot_sync(0xffffffffu, a.x != 0.f);
        if (a.x != 0.f) { int p = base + __popc(m & lt); if (p < CAP) idx[p] = (unsigned short)col; }
        base += __popc(m);
        m = __ballot_sync(0xffffffffu, a.y != 0.f);
        if (a.y != 0.f) { int p = base + __popc(m & lt); if (p < CAP) idx[p] = (unsigned short)(col + 1); }
        base += __popc(m);
        m = __ballot_sync(0xffffffffu, a.z != 0.f);
        if (a.z != 0.f) { int p = base + __popc(m & lt); if (p < CAP) idx[p] = (unsigned short)(col + 2); }
        base += __popc(m);
        m = __ballot_sync(0xffffffffu, a.w != 0.f);
        if (a.w != 0.f) { int p = base + __popc(m & lt); if (p < CAP) idx[p] = (unsigned short)(col + 3); }
        base += __popc(m);
    }
    #pragma unroll
    for (int o = 16; o; o >>= 1) s += __shfl_xor_sync(0xffffffffu, s, o);
    if (lane == 0) { g_cnt[warp] = base; g_dinv[warp] = rsqrtf(s + 1.f); }
}

// ---------------- xs[b][j][:] = d_j * x[b][j][:] ----------------
__global__ void k_xscale(const float* __restrict__ x) {
    size_t i = (size_t)blockIdx.x * blockDim.x + threadIdx.x;   // float4 index
    int row = (int)(i >> 5);
    float d = g_dinv[row];
    float4 v = ((const float4*)x)[i];
    v.x *= d; v.y *= d; v.z *= d; v.w *= d;
    ((float4*)g_xs)[i] = v;
}

// ---------------- agg[b][i][:] = d_i * (xs[i] + sum_{j in idx} xs[j]) ----------------
__global__ void k_gather(const float* __restrict__ A) {
    int warp = (blockIdx.x * blockDim.x + threadIdx.x) >> 5;
    int lane = threadIdx.x & 31;
    const float4* xs4 = (const float4*)g_xs;
    size_t rowbase = (size_t)warp * 32;
    float4 acc = xs4[rowbase + lane];   // +I (diagonal) term: d_i x[i]
    int cnt = g_cnt[warp];
    size_t bb = ((size_t)(warp >> 12)) * NN * 32;   // batch base in float4s
    if (cnt <= CAP) {
        const unsigned short* idx = g_idx + (size_t)warp * CAP;
        int p = 0;
        while (p < cnt) {
            int jv = (p + lane < cnt) ? (int)idx[p + lane] : 0;
            int np = min(32, cnt - p);
            int q = 0;
            for (; q + 4 <= np; q += 4) {
                int j0 = __shfl_sync(0xffffffffu, jv, q);
                int j1 = __shfl_sync(0xffffffffu, jv, q + 1);
                int j2 = __shfl_sync(0xffffffffu, jv, q + 2);
                int j3 = __shfl_sync(0xffffffffu, jv, q + 3);
                float4 v0 = xs4[bb + (size_t)j0 * 32 + lane];
                float4 v1 = xs4[bb + (size_t)j1 * 32 + lane];
                float4 v2 = xs4[bb + (size_t)j2 * 32 + lane];
                float4 v3 = xs4[bb + (size_t)j3 * 32 + lane];
                acc.x += (v0.x + v1.x) + (v2.x + v3.x);
                acc.y += (v0.y + v1.y) + (v2.y + v3.y);
                acc.z += (v0.z + v1.z) + (v2.z + v3.z);
                acc.w += (v0.w + v1.w) + (v2.w + v3.w);
            }
            for (; q < np; q++) {
                int j = __shfl_sync(0xffffffffu, jv, q);
                float4 v = xs4[bb + (size_t)j * 32 + lane];
                acc.x += v.x; acc.y += v.y; acc.z += v.z; acc.w += v.w;
            }
            p += 32;
        }
    } else {
        const float* Ar = A + (size_t)warp * NN;
        for (int j0 = 0; j0 < NN; j0 += 32) {
            float a = Ar[j0 + lane];
            unsigned m = __ballot_sync(0xffffffffu, a != 0.f);
            while (m) {
                int q = __ffs(m) - 1; m &= m - 1;
                float4 v = xs4[bb + (size_t)(j0 + q) * 32 + lane];
                acc.x += v.x; acc.y += v.y; acc.z += v.z; acc.w += v.w;
            }
        }
    }
    float di = g_dinv[warp];
    acc.x *= di; acc.y *= di; acc.z *= di; acc.w *= di;
    ((float4*)g_agg)[rowbase + lane] = acc;
}

// ---------------- conv1d (NCH, pad 1): dyn[b][o][t] ----------------
__global__ void k_conv(const float* __restrict__ x, const float* __restrict__ cw,
                       const float* __restrict__ cb) {
    int b = blockIdx.x >> 7, o = blockIdx.x & 127, t = threadIdx.x;
    __shared__ float w[HID * 3];
    for (int i = threadIdx.x; i < HID * 3; i += blockDim.x) w[i] = cw[o * HID * 3 + i];
    __syncthreads();
    float acc = cb[o];
    const float* xb = x + ((size_t)b * NN + (NN - HID)) * HID;
    for (int i = 0; i < HID; i++) {
        const float* xr = xb + i * HID;
        float xm = (t > 0) ? xr[t - 1] : 0.f;
        float x0 = xr[t];
        float xp = (t < HID - 1) ? xr[t + 1] : 0.f;
        acc += xm * w[i * 3] + x0 * w[i * 3 + 1] + xp * w[i * 3 + 2];
    }
    g_dyn[(b * HID + o) * HID + t] = acc;
}

// ---------------- zx[b][t][g] = dyn[b][t] @ w_ih^T + b_ih + b_hh ----------------
__global__ void k_zx(const float* __restrict__ wih, const float* __restrict__ bih,
                     const float* __restrict__ bhh) {
    int b = blockIdx.x >> 2;
    int t0 = (blockIdx.x & 3) * 32;
    int g = threadIdx.x;
    __shared__ float4 dsh[32 * 32];   // [tt][f4]
    for (int i = threadIdx.x; i < 32 * 32; i += blockDim.x)
        dsh[i] = ((const float4*)g_dyn)[(b * HID + t0 + (i >> 5)) * 32 + (i & 31)];
    __syncthreads();
    float acc[32];
    #pragma unroll
    for (int tt = 0; tt < 32; tt++) acc[tt] = 0.f;
    const float4* w4 = (const float4*)wih + g * 32;
    for (int c = 0; c < 4; c++) {
        float4 wv[8];
        #pragma unroll
        for (int j = 0; j < 8; j++) wv[j] = w4[c * 8 + j];
        #pragma unroll
        for (int tt = 0; tt < 32; tt++) {
            float s = 0.f;
            #pragma unroll
            for (int j = 0; j < 8; j++) {
                float4 dv = dsh[tt * 32 + c * 8 + j];
                s += wv[j].x * dv.x + wv[j].y * dv.y + wv[j].z * dv.z + wv[j].w * dv.w;
            }
            acc[tt] += s;
        }
    }
    float bias = bih[g] + bhh[g];
    for (int tt = 0; tt < 32; tt++) g_zx[(b * HID + t0 + tt) * G4 + g] = acc[tt] + bias;
}

// ---------------- LSTM: 2-CTA cluster per batch, weights in registers ----------------
__global__ void __launch_bounds__(512, 1) __cluster_dims__(2, 1, 1)
k_lstm(const float* __restrict__ whh) {
    int b = blockIdx.x >> 1;
    int r = blockIdx.x & 1;
    int tid = threadIdx.x;
    int lg = tid & 255;
    int hh = tid >> 8;
    int cls = lg >> 6;           // 0=i 1=f 2=g 3=o
    int kk = lg & 63;
    int gate = cls * 128 + 64 * r + kk;

    __shared__ float hbuf[2][HID];
    __shared__ float zA[256];
    __shared__ float zB[256];
    __shared__ __align__(8) unsigned int flg[2][2];   // [parity][epi-warp]

    ull w[32];
    const float4* w4 = (const float4*)whh + (size_t)gate * 32 + hh * 16;
    #pragma unroll
    for (int j = 0; j < 16; j++) {
        float4 v = w4[j];
        w[2 * j]     = pk(v.x, v.y);
        w[2 * j + 1] = pk(v.z, v.w);
    }
    if (tid < HID) { hbuf[0][tid] = 0.f; hbuf[1][tid] = 0.f; }
    if (tid < 4) ((unsigned int*)flg)[tid] = 0u;

    uint32_t lf0 = (uint32_t)__cvta_generic_to_shared(&flg[0][0]);
    uint32_t lf1 = (uint32_t)__cvta_generic_to_shared(&flg[1][0]);
    uint32_t ph0 = 0, ph1 = 0, pf0 = 0, pf1 = 0;
    if (tid < 64) {
        int hidx = 64 * r + tid;
        uint32_t a0 = (uint32_t)__cvta_generic_to_shared(&hbuf[0][hidx]);
        uint32_t a1 = (uint32_t)__cvta_generic_to_shared(&hbuf[1][hidx]);
        int wv = tid >> 5;
        uint32_t f0 = (uint32_t)__cvta_generic_to_shared(&flg[0][wv]);
        uint32_t f1 = (uint32_t)__cvta_generic_to_shared(&flg[1][wv]);
        asm("mapa.shared::cluster.u32 %0, %1, %2;" : "=r"(ph0) : "r"(a0), "r"(r ^ 1));
        asm("mapa.shared::cluster.u32 %0, %1, %2;" : "=r"(ph1) : "r"(a1), "r"(r ^ 1));
        asm("mapa.shared::cluster.u32 %0, %1, %2;" : "=r"(pf0) : "r"(f0), "r"(r ^ 1));
        asm("mapa.shared::cluster.u32 %0, %1, %2;" : "=r"(pf1) : "r"(f1), "r"(r ^ 1));
    }
    __syncthreads();
    asm volatile("barrier.cluster.arrive.aligned;" ::: "memory");
    asm volatile("barrier.cluster.wait.aligned;" ::: "memory");

    float c = 0.f;
    const float* zxp = g_zx + (size_t)b * HID * G4 + gate;
    float z0 = zxp[0];
    bool spinner = (hh != r);

    for (int step = 0; step < HID; step++) {
        if (spinner) {
            uint32_t fa = (step & 1) ? lf1 : lf0;
            ull v; unsigned lo, hi;
            do {
                asm volatile("ld.acquire.cluster.shared::cta.u64 %0, [%1];"
                             : "=l"(v) : "r"(fa) : "memory");
                lo = (unsigned)v; hi = (unsigned)(v >> 32);
            } while ((int)lo < step || (int)hi < step);
        }
        float znext = (step < HID - 1) ? zxp[(step + 1) * G4] : 0.f;
        const ulonglong2* h2 = (const ulonglong2*)(&hbuf[step & 1][hh * 64]);
        ull a0 = 0, a1 = 0, a2 = 0, a3 = 0;
        #pragma unroll
        for (int j = 0; j < 8; j++) {
            ulonglong2 hv0 = h2[2 * j];
            ulonglong2 hv1 = h2[2 * j + 1];
            fma2(a0, w[4 * j],     hv0.x);
            fma2(a1, w[4 * j + 1], hv0.y);
            fma2(a2, w[4 * j + 2], hv1.x);
            fma2(a3, w[4 * j + 3], hv1.y);
        }
        float2 s0 = unpk(a0), s1 = unpk(a1), s2 = unpk(a2), s3 = unpk(a3);
        float z = ((s0.x + s0.y) + (s1.x + s1.y)) + ((s2.x + s2.y) + (s3.x + s3.y));
        if (hh == 0) zA[lg] = z + z0;
        else         zB[lg] = z;
        z0 = znext;
        __syncthreads();
        int nxt = (step + 1) & 1;
        if (tid < 64) {
            float zi = zA[tid]       + zB[tid];
            float zf = zA[64 + tid]  + zB[64 + tid];
            float zg = zA[128 + tid] + zB[128 + tid];
            float zo = zA[192 + tid] + zB[192 + tid];
            float iv = sigf(zi);
            float fv = sigf(zf);
            float gv = tanh_fast(zg);
            float ov = sigf(zo);
            c = fv * c + iv * gv;
            float h = ov * tanh_fast(c);
            int hidx = 64 * r + tid;
            hbuf[nxt][hidx] = h;
            uint32_t pa = nxt ? ph1 : ph0;
            asm volatile("st.shared::cluster.f32 [%0], %1;" :: "r"(pa), "f"(h) : "memory");
            g_lwm[((size_t)b * HID + step) * HID + hidx] = h;
            __syncwarp();
            if ((tid & 31) == 0) {
                uint32_t fa = nxt ? pf1 : pf0;
                asm volatile("st.release.cluster.shared::cluster.u32 [%0], %1;"
                             :: "r"(fa), "r"(step + 1) : "memory");
            }
        }
        __syncthreads();
    }
    asm volatile("barrier.cluster.arrive.aligned;" ::: "memory");
    asm volatile("barrier.cluster.wait.aligned;" ::: "memory");
}

// ---------------- out[b][i][h] = sigmoid(agg[b][i] @ lw[b]) ----------------
__global__ void k_out(float* __restrict__ out) {
    int b = blockIdx.x >> 7;
    int r0 = (blockIdx.x & 127) * 32;
    int h = threadIdx.x;
    __shared__ float4 as4[32 * 32];     // [r][f4]
    for (int i = threadIdx.x; i < 32 * 32; i += blockDim.x)
        as4[i] = ((const float4*)g_agg)[((size_t)b * NN + r0 + (i >> 5)) * 32 + (i & 31)];
    __syncthreads();
    float acc[32];
    #pragma unroll
    for (int r = 0; r < 32; r++) acc[r] = 0.f;
    for (int f4 = 0; f4 < 32; f4++) {
        float l0 = g_lwm[(b * HID + 4 * f4 + 0) * HID + h];
        float l1 = g_lwm[(b * HID + 4 * f4 + 1) * HID + h];
        float l2 = g_lwm[(b * HID + 4 * f4 + 2) * HID + h];
        float l3 = g_lwm[(b * HID + 4 * f4 + 3) * HID + h];
        #pragma unroll
        for (int r = 0; r < 32; r++) {
            float4 av = as4[r * 32 + f4];
            acc[r] += av.x * l0 + av.y * l1 + av.z * l2 + av.w * l3;
        }
    }
    for (int r = 0; r < 32; r++)
        out[((size_t)b * NN + r0 + r) * HID + h] = sigf(acc[r]);
}

// ---------------- launch: A-path on side stream, LSTM chain on main ----------------
extern "C" void kernel_launch(void* const* d_in, const int* in_sizes, int n_in,
                              void* d_out, int out_size) {
    const float* x   = (const float*)d_in[0];
    const float* A   = (const float*)d_in[1];
    const float* cw  = (const float*)d_in[2];
    const float* cb  = (const float*)d_in[3];
    const float* wih = (const float*)d_in[4];
    const float* whh = (const float*)d_in[5];
    const float* bih = (const float*)d_in[6];
    const float* bhh = (const float*)d_in[7];
    float* out = (float*)d_out;

    static cudaStream_t s2 = nullptr;
    static cudaEvent_t eF = nullptr, eJ = nullptr;
    if (!s2) {
        cudaStreamCreateWithFlags(&s2, cudaStreamNonBlocking);
        cudaEventCreateWithFlags(&eF, cudaEventDisableTiming);
        cudaEventCreateWithFlags(&eJ, cudaEventDisableTiming);
    }

    // fork: entire A-path (rowsum -> xscale -> gather) overlaps the LSTM chain
    cudaEventRecord(eF, 0);
    cudaStreamWaitEvent(s2, eF, 0);
    k_rowsum<<<BATCH * NN / 8, 256, 0, s2>>>(A);
    k_xscale<<<(BATCH * NN * HID / 4) / 256, 256, 0, s2>>>(x);
    k_gather<<<BATCH * NN / 8, 256, 0, s2>>>(A);
    cudaEventRecord(eJ, s2);

    k_conv<<<BATCH * HID, HID>>>(x, cw, cb);
    k_zx<<<16, 512>>>(wih, bih, bhh);
    k_lstm<<<2 * BATCH, 512>>>(whh);

    cudaStreamWaitEvent(0, eJ, 0);
    k_out<<<BATCH * (NN / 32), HID>>>(out);
}